// round 4
// baseline (speedup 1.0000x reference)
#include <cuda_runtime.h>
#include <cstdint>

#define NS 2
#define NB 8
#define NC 32
#define NH 128
#define NW 128
#define NM 32
#define RH 64
#define RW 64

// One block = one (n, bm, c) output tile of 64x64 floats (16 KB).
// 256 threads; each thread writes 4 float4s at rows r0, r0+16, r0+32, r0+48.
// Loads fetch EXACTLY the needed window [x1+c0, x1+c0+4) using the widest
// alignment-legal pieces (x1 parity is block-uniform): no redundant sectors.

__global__ __launch_bounds__(256) void roi_patch_kernel(
    const float* __restrict__ fm,
    const int*   __restrict__ boxes,
    float*       __restrict__ out)
{
    const int blk = blockIdx.x;
    const int c   = blk & 31;
    const int bm  = (blk >> 5) & 255;
    const int n   = blk >> 13;
    const int b   = bm >> 5;
    const int m   = bm & 31;

    const int4 box = __ldg(reinterpret_cast<const int4*>(boxes)
                           + (n * NB + b) * NM + m);
    const int x1   = box.x;
    const int y1   = box.y;
    const int wbox = box.z - x1;   // valid cols: cc < wbox  (8..64)
    const int hbox = box.w - y1;   // valid rows: r  < hbox  (8..64)

    const int lane16 = threadIdx.x & 15;
    const int r0     = threadIdx.x >> 4;     // 0..15
    const int c0     = lane16 << 2;

    const bool p0 = (c0 + 0) < wbox;
    const bool p1 = (c0 + 1) < wbox;
    const bool p2 = (c0 + 2) < wbox;
    const bool p3 = (c0 + 3) < wbox;

    const float* s0 = fm
        + (((size_t)(n * NB + b) * NC + c) * NH + (y1 + r0)) * NW
        + x1 + c0;
    float* dst = out + ((size_t)blk << 12) + (r0 << 6) + c0;

    if ((x1 & 1) == 0) {
        // 8B-aligned window: two LDG.64 pieces.
        #pragma unroll
        for (int i = 0; i < 4; ++i) {
            const int r = r0 + (i << 4);
            float4 v = make_float4(0.f, 0.f, 0.f, 0.f);
            if (r < hbox) {
                const float* s = s0 + (i << 4) * NW;
                if (p0) {
                    const float2 lo = __ldg(reinterpret_cast<const float2*>(s));
                    v.x = lo.x; v.y = lo.y;
                }
                if (p2) {
                    const float2 hi = __ldg(reinterpret_cast<const float2*>(s + 2));
                    v.z = hi.x; v.w = hi.y;
                }
                if (!p1) v.y = 0.f;
                if (!p3) v.w = 0.f;
            }
            __stcs(reinterpret_cast<float4*>(dst + ((i << 4) << 6)), v);
        }
    } else {
        // 4B-aligned window: LDG.32 + LDG.64 (s+1 is 8B-aligned) + LDG.32.
        #pragma unroll
        for (int i = 0; i < 4; ++i) {
            const int r = r0 + (i << 4);
            float4 v = make_float4(0.f, 0.f, 0.f, 0.f);
            if (r < hbox) {
                const float* s = s0 + (i << 4) * NW;
                if (p0) v.x = __ldg(s);
                if (p1) {
                    const float2 mid = __ldg(reinterpret_cast<const float2*>(s + 1));
                    v.y = mid.x; v.z = mid.y;
                }
                if (p3) v.w = __ldg(s + 3);
                if (!p2) v.z = 0.f;
            }
            __stcs(reinterpret_cast<float4*>(dst + ((i << 4) << 6)), v);
        }
    }
}

extern "C" void kernel_launch(void* const* d_in, const int* in_sizes, int n_in,
                              void* d_out, int out_size)
{
    const float* fm    = (const float*)d_in[0];
    const int*   boxes = (const int*)d_in[1];
    float*       out   = (float*)d_out;

    const int blocks = NS * NB * NM * NC;   // 16384 tiles
    roi_patch_kernel<<<blocks, 256>>>(fm, boxes, out);
}

// round 5
// speedup vs baseline: 1.0007x; 1.0007x over previous
#include <cuda_runtime.h>
#include <cstdint>

#define NS 2
#define NB 8
#define NC 32
#define NH 128
#define NW 128
#define NM 32
#define RH 64
#define RW 64

// One block = one (n, bm, c) output tile of 64x64 floats (16 KB).
// 256 threads; each thread writes 4 float4s at rows r0, r0+16, r0+32, r0+48.
// Phase 1: issue ALL load pieces (8 independent LDG.64s) -> high MLP.
// Phase 2: issue the 4 STG.128.CS back-to-back -> write bursts.

__global__ __launch_bounds__(256) void roi_patch_kernel(
    const float* __restrict__ fm,
    const int*   __restrict__ boxes,
    float*       __restrict__ out)
{
    const int blk = blockIdx.x;
    const int c   = blk & 31;
    const int bm  = (blk >> 5) & 255;
    const int n   = blk >> 13;
    const int b   = bm >> 5;
    const int m   = bm & 31;

    const int4 box = __ldg(reinterpret_cast<const int4*>(boxes)
                           + (n * NB + b) * NM + m);
    const int x1   = box.x;
    const int y1   = box.y;
    const int wbox = box.z - x1;   // valid cols: cc < wbox  (8..64)
    const int hbox = box.w - y1;   // valid rows: r  < hbox  (8..64)

    const int lane16 = threadIdx.x & 15;
    const int r0     = threadIdx.x >> 4;     // 0..15
    const int c0     = lane16 << 2;

    const bool p0 = (c0 + 0) < wbox;
    const bool p1 = (c0 + 1) < wbox;
    const bool p2 = (c0 + 2) < wbox;
    const bool p3 = (c0 + 3) < wbox;

    const float* s0 = fm
        + (((size_t)(n * NB + b) * NC + c) * NH + (y1 + r0)) * NW
        + x1 + c0;
    float* dst = out + ((size_t)blk << 12) + (r0 << 6) + c0;

    const float2 z2 = make_float2(0.f, 0.f);
    float2 lo[4], hi[4];

    if ((x1 & 1) == 0) {
        // 8B-aligned window: two LDG.64 per row, all 8 issued before any store.
        #pragma unroll
        for (int i = 0; i < 4; ++i) {
            const bool rv = (r0 + (i << 4)) < hbox;
            const float* s = s0 + (i << 4) * NW;
            lo[i] = (rv && p0) ? __ldg(reinterpret_cast<const float2*>(s))     : z2;
            hi[i] = (rv && p2) ? __ldg(reinterpret_cast<const float2*>(s + 2)) : z2;
        }
    } else {
        // 4B-aligned: LDG.32 + LDG.64 + LDG.32 per row, all issued up front.
        #pragma unroll
        for (int i = 0; i < 4; ++i) {
            const bool rv = (r0 + (i << 4)) < hbox;
            const float* s = s0 + (i << 4) * NW;
            float x = (rv && p0) ? __ldg(s) : 0.f;
            float2 mid = (rv && p1) ? __ldg(reinterpret_cast<const float2*>(s + 1)) : z2;
            float w = (rv && p3) ? __ldg(s + 3) : 0.f;
            lo[i] = make_float2(x, mid.x);
            hi[i] = make_float2(mid.y, w);
        }
    }

    #pragma unroll
    for (int i = 0; i < 4; ++i) {
        float4 v;
        v.x = lo[i].x;
        v.y = p1 ? lo[i].y : 0.f;
        v.z = p2 ? hi[i].x : 0.f;
        v.w = p3 ? hi[i].y : 0.f;
        __stcs(reinterpret_cast<float4*>(dst + ((i << 4) << 6)), v);
    }
}

extern "C" void kernel_launch(void* const* d_in, const int* in_sizes, int n_in,
                              void* d_out, int out_size)
{
    const float* fm    = (const float*)d_in[0];
    const int*   boxes = (const int*)d_in[1];
    float*       out   = (float*)d_out;

    const int blocks = NS * NB * NM * NC;   // 16384 tiles
    roi_patch_kernel<<<blocks, 256>>>(fm, boxes, out);
}